// round 1
// baseline (speedup 1.0000x reference)
#include <cuda_runtime.h>
#include <cstdint>

// Problem constants (fixed by the reference)
#define NFINE   1000000
#define NCOARSE 250000
#define VAL_DIM 32
#define FE      9
#define KDIM    (FE * VAL_DIM)   // 288
#define NF      64

// Tiling
#define BLOCK_M 256              // fine rows per CTA iteration
#define THREADS 256              // 8 warps; each warp: m32 x n64
#define WSTRIDE 72               // padded weight row stride (floats) -> conflict-free B LDS
#define SMEM_BYTES (KDIM * WSTRIDE * 4 + BLOCK_M * FE * 4)  // 82944 + 9216 = 92160

__global__ void __launch_bounds__(THREADS, 2)
finefy_tf32_kernel(const float* __restrict__ coarse,
                   const int*   __restrict__ nbr,
                   const float* __restrict__ weight,
                   float*       __restrict__ out,
                   int numTiles)
{
    extern __shared__ uint32_t sm_[];
    uint32_t* ws   = sm_;                               // [KDIM][WSTRIDE] tf32 weight
    int*      idxs = (int*)(sm_ + KDIM * WSTRIDE);      // [BLOCK_M][FE]

    const int tid  = threadIdx.x;
    const int lane = tid & 31;
    const int wid  = tid >> 5;
    const int qr   = lane >> 2;   // 0..7  (row-in-group / B n-component)
    const int qc   = lane & 3;    // 0..3  (k-in-group / C col pair)

    // Load weight -> tf32 (round-to-nearest) into padded smem, once per CTA.
    for (int i = tid; i < KDIM * NF; i += THREADS) {
        int k = i >> 6, n = i & 63;
        uint32_t t;
        asm("cvt.rna.tf32.f32 %0, %1;" : "=r"(t) : "f"(weight[i]));
        ws[k * WSTRIDE + n] = t;
    }

    for (int tile = blockIdx.x; tile < numTiles; tile += gridDim.x) {
        const int rowbase = tile * BLOCK_M;

        __syncthreads();  // previous iteration done with idxs (also orders weight on iter 0)
        {
            const long g0   = (long)rowbase * FE;
            const long gmax = (long)NFINE * FE;
            #pragma unroll
            for (int i = tid; i < BLOCK_M * FE; i += THREADS) {
                long g = g0 + i;
                idxs[i] = (g < gmax) ? nbr[g] : 0;
            }
        }
        __syncthreads();

        // Per-warp accumulators: 8 n-tiles x 2 m16-subtiles x 4 regs = m32 x n64
        float acc[16][4];
        #pragma unroll
        for (int i = 0; i < 16; ++i) {
            acc[i][0] = 0.f; acc[i][1] = 0.f; acc[i][2] = 0.f; acc[i][3] = 0.f;
        }

        const int lr = (wid << 5) + qr;   // local row of this thread's fragment anchor

        for (int j = 0; j < FE; ++j) {
            // One coarse row pointer per m16-half this thread touches
            const float* p0 = coarse + (size_t)idxs[(lr     ) * FE + j] * VAL_DIM + qc;
            const float* p1 = coarse + (size_t)idxs[(lr +  8) * FE + j] * VAL_DIM + qc;
            const float* p2 = coarse + (size_t)idxs[(lr + 16) * FE + j] * VAL_DIM + qc;
            const float* p3 = coarse + (size_t)idxs[(lr + 24) * FE + j] * VAL_DIM + qc;

            #pragma unroll
            for (int kk = 0; kk < 4; ++kk) {          // 4 k8-steps per neighbor (32 dims)
                // A fragments (m16n8k8.tf32 layout), raw fp32 bits (HW uses tf32 bits)
                uint32_t a0 = __float_as_uint(__ldg(p0 + kk * 8));
                uint32_t a1 = __float_as_uint(__ldg(p1 + kk * 8));
                uint32_t a2 = __float_as_uint(__ldg(p0 + kk * 8 + 4));
                uint32_t a3 = __float_as_uint(__ldg(p1 + kk * 8 + 4));
                uint32_t a4 = __float_as_uint(__ldg(p2 + kk * 8));
                uint32_t a5 = __float_as_uint(__ldg(p3 + kk * 8));
                uint32_t a6 = __float_as_uint(__ldg(p2 + kk * 8 + 4));
                uint32_t a7 = __float_as_uint(__ldg(p3 + kk * 8 + 4));

                const uint32_t* wrow = ws + (j * VAL_DIM + kk * 8 + qc) * WSTRIDE + qr;

                #pragma unroll
                for (int t = 0; t < 8; ++t) {         // 8 n8 tiles = full N=64
                    uint32_t b0 = wrow[t * 8];
                    uint32_t b1 = wrow[t * 8 + 4 * WSTRIDE];
                    asm volatile(
                        "mma.sync.aligned.m16n8k8.row.col.f32.tf32.tf32.f32 "
                        "{%0,%1,%2,%3}, {%4,%5,%6,%7}, {%8,%9}, {%0,%1,%2,%3};"
                        : "+f"(acc[2*t][0]), "+f"(acc[2*t][1]),
                          "+f"(acc[2*t][2]), "+f"(acc[2*t][3])
                        : "r"(a0), "r"(a1), "r"(a2), "r"(a3), "r"(b0), "r"(b1));
                    asm volatile(
                        "mma.sync.aligned.m16n8k8.row.col.f32.tf32.tf32.f32 "
                        "{%0,%1,%2,%3}, {%4,%5,%6,%7}, {%8,%9}, {%0,%1,%2,%3};"
                        : "+f"(acc[2*t+1][0]), "+f"(acc[2*t+1][1]),
                          "+f"(acc[2*t+1][2]), "+f"(acc[2*t+1][3])
                        : "r"(a4), "r"(a5), "r"(a6), "r"(a7), "r"(b0), "r"(b1));
                }
            }
        }

        // Epilogue: coalesced float2 stores (each quad covers a 32B sector)
        #pragma unroll
        for (int s = 0; s < 2; ++s) {
            #pragma unroll
            for (int h = 0; h < 2; ++h) {
                int r = rowbase + (wid << 5) + s * 16 + h * 8 + qr;
                if (r < NFINE) {
                    float2* po = (float2*)(out + (size_t)r * NF + qc * 2);
                    #pragma unroll
                    for (int t = 0; t < 8; ++t) {
                        po[t * 4] = make_float2(acc[2*t + s][2*h], acc[2*t + s][2*h + 1]);
                    }
                }
            }
        }
    }
}

extern "C" void kernel_launch(void* const* d_in, const int* in_sizes, int n_in,
                              void* d_out, int out_size)
{
    const float* coarse = (const float*)d_in[0];   // [250000, 32] f32
    const int*   nbr    = (const int*)  d_in[1];   // [1000000, 9] i32
    const float* weight = (const float*)d_in[2];   // [288, 64] f32
    float*       out    = (float*)d_out;           // [1000000, 64] f32

    cudaFuncSetAttribute(finefy_tf32_kernel,
                         cudaFuncAttributeMaxDynamicSharedMemorySize, SMEM_BYTES);

    const int numTiles = (NFINE + BLOCK_M - 1) / BLOCK_M;   // 3907
    const int grid = 304;                                   // 2 CTAs/SM x 152 SMs (persistent)
    finefy_tf32_kernel<<<grid, THREADS, SMEM_BYTES>>>(coarse, nbr, weight, out, numTiles);
}

// round 2
// speedup vs baseline: 1.1894x; 1.1894x over previous
#include <cuda_runtime.h>
#include <cstdint>

#define NFINE   1000000
#define VAL_DIM 32
#define FE      9
#define KDIM    (FE * VAL_DIM)
#define NF      64

#define BLOCK_M 256
#define THREADS 256
#define WSTRIDE 72     // B row stride (floats), conflict-free B LDS
#define ASTRIDE 36     // A slab row stride (floats): bank=(4r+c)%32, conflict-free

// smem (u32 units): B | A slab double buffer | idx
#define WS_OFF   0
#define WS_U32   (KDIM * WSTRIDE)            // 20736
#define A_OFF    (WS_OFF + WS_U32)
#define A_U32    (BLOCK_M * ASTRIDE)         // 9216 per slab buffer
#define IDX_OFF  (A_OFF + 2 * A_U32)         // 39168
#define IDX_U32  (BLOCK_M * FE)              // 2304
#define SMEM_U32 (IDX_OFF + IDX_U32)         // 41472
#define SMEM_BYTES (SMEM_U32 * 4)            // 165888 B -> 1 CTA/SM

__device__ __forceinline__ void cp_commit() { asm volatile("cp.async.commit_group;"); }
template<int N> __device__ __forceinline__ void cp_wait() {
    asm volatile("cp.async.wait_group %0;" :: "n"(N));
}

// Gather one neighbor slab j: 256 rows x 128B, 9 cp.async(16B) per thread.
__device__ __forceinline__ void issue_slab(const float* __restrict__ coarse,
                                           const int* __restrict__ sidx, int j,
                                           uint32_t a_addr)
{
    // op o = r*8 + seg, o = tid + i*256, total 2048 ops
    #pragma unroll
    for (int i = 0; i < 8; ++i) {
        int o   = i * THREADS + threadIdx.x;
        int r   = o >> 3;
        int seg = o & 7;
        int idx = sidx[r * FE + j];
        const char* src = (const char*)coarse + ((size_t)(unsigned)idx << 7) + (seg << 4);
        uint32_t dst = a_addr + (uint32_t)r * (ASTRIDE * 4) + (uint32_t)(seg << 4);
        asm volatile("cp.async.cg.shared.global [%0], [%1], 16;" :: "r"(dst), "l"(src));
    }
}

__global__ void __launch_bounds__(THREADS, 1)
finefy_tf32_kernel(const float* __restrict__ coarse,
                   const int*   __restrict__ nbr,
                   const float* __restrict__ weight,
                   float*       __restrict__ out,
                   int numTiles)
{
    extern __shared__ uint32_t sm_[];
    uint32_t* ws = sm_ + WS_OFF;
    int* sidx    = (int*)(sm_ + IDX_OFF);

    const uint32_t smem_base = (uint32_t)__cvta_generic_to_shared(sm_);
    const uint32_t a_base    = smem_base + A_OFF * 4;
    const int tid  = threadIdx.x;
    const int lane = tid & 31;
    const int wid  = tid >> 5;
    const int qr   = lane >> 2;
    const int qc   = lane & 3;

    for (int i = tid; i < KDIM * NF; i += THREADS) {
        int k = i >> 6, n = i & 63;
        uint32_t t;
        asm("cvt.rna.tf32.f32 %0, %1;" : "=r"(t) : "f"(weight[i]));
        ws[k * WSTRIDE + n] = t;
    }

    for (int tile = blockIdx.x; tile < numTiles; tile += gridDim.x) {
        const int rowbase = tile * BLOCK_M;

        // Stage idx slab (coalesced 4B cp.async), then prime slab j=0.
        __syncthreads();   // prior iteration fully done with smem
        {
            const size_t gmax = (size_t)NFINE * FE - 1;
            const size_t g0   = (size_t)rowbase * FE;
            #pragma unroll
            for (int i = tid; i < BLOCK_M * FE; i += THREADS) {
                size_t g = g0 + i; if (g > gmax) g = gmax;
                asm volatile("cp.async.ca.shared.global [%0], [%1], 4;"
                             :: "r"(smem_base + (IDX_OFF + i) * 4), "l"(nbr + g));
            }
        }
        cp_commit();
        cp_wait<0>();
        __syncthreads();

        issue_slab(coarse, sidx, 0, a_base);            // slab 0 -> buf 0
        cp_commit();

        float acc[16][4];
        #pragma unroll
        for (int i = 0; i < 16; ++i) {
            acc[i][0] = 0.f; acc[i][1] = 0.f; acc[i][2] = 0.f; acc[i][3] = 0.f;
        }

        #pragma unroll
        for (int j = 0; j < FE; ++j) {
            if (j + 1 < FE) {
                issue_slab(coarse, sidx, j + 1, a_base + (j & 1 ? 0 : A_U32 * 4));
                cp_commit();
                cp_wait<1>();   // slab j landed; slab j+1 in flight
            } else {
                cp_wait<0>();
            }
            __syncthreads();

            const uint32_t* As = sm_ + A_OFF + (j & 1) * A_U32;
            const uint32_t* ar = As + (wid * 32 + qr) * ASTRIDE + qc;

            #pragma unroll
            for (int kk = 0; kk < 4; ++kk) {
                const int c = kk * 8;
                uint32_t a0 = ar[c];
                uint32_t a2 = ar[c + 4];
                uint32_t a1 = ar[c + 8  * ASTRIDE];
                uint32_t a3 = ar[c + 8  * ASTRIDE + 4];
                uint32_t a4 = ar[c + 16 * ASTRIDE];
                uint32_t a6 = ar[c + 16 * ASTRIDE + 4];
                uint32_t a5 = ar[c + 24 * ASTRIDE];
                uint32_t a7 = ar[c + 24 * ASTRIDE + 4];

                const uint32_t* wrow = ws + (j * VAL_DIM + kk * 8 + qc) * WSTRIDE + qr;

                #pragma unroll
                for (int t = 0; t < 8; ++t) {
                    uint32_t b0 = wrow[t * 8];
                    uint32_t b1 = wrow[t * 8 + 4 * WSTRIDE];
                    asm volatile(
                        "mma.sync.aligned.m16n8k8.row.col.f32.tf32.tf32.f32 "
                        "{%0,%1,%2,%3}, {%4,%5,%6,%7}, {%8,%9}, {%0,%1,%2,%3};"
                        : "+f"(acc[2*t][0]), "+f"(acc[2*t][1]),
                          "+f"(acc[2*t][2]), "+f"(acc[2*t][3])
                        : "r"(a0), "r"(a1), "r"(a2), "r"(a3), "r"(b0), "r"(b1));
                    asm volatile(
                        "mma.sync.aligned.m16n8k8.row.col.f32.tf32.tf32.f32 "
                        "{%0,%1,%2,%3}, {%4,%5,%6,%7}, {%8,%9}, {%0,%1,%2,%3};"
                        : "+f"(acc[2*t+1][0]), "+f"(acc[2*t+1][1]),
                          "+f"(acc[2*t+1][2]), "+f"(acc[2*t+1][3])
                        : "r"(a4), "r"(a5), "r"(a6), "r"(a7), "r"(b0), "r"(b1));
                }
            }
            __syncthreads();   // all warps done with slab j before it is overwritten
        }

        // Epilogue: coalesced float2 stores
        #pragma unroll
        for (int s = 0; s < 2; ++s) {
            #pragma unroll
            for (int h = 0; h < 2; ++h) {
                int r = rowbase + (wid << 5) + s * 16 + h * 8 + qr;
                if (r < NFINE) {
                    float2* po = (float2*)(out + (size_t)r * NF + qc * 2);
                    #pragma unroll
                    for (int t = 0; t < 8; ++t)
                        po[t * 4] = make_float2(acc[2*t + s][2*h], acc[2*t + s][2*h + 1]);
                }
            }
        }
    }
}

extern "C" void kernel_launch(void* const* d_in, const int* in_sizes, int n_in,
                              void* d_out, int out_size)
{
    const float* coarse = (const float*)d_in[0];
    const int*   nbr    = (const int*)  d_in[1];
    const float* weight = (const float*)d_in[2];
    float*       out    = (float*)d_out;

    cudaFuncSetAttribute(finefy_tf32_kernel,
                         cudaFuncAttributeMaxDynamicSharedMemorySize, SMEM_BYTES);

    int nsm = 148;
    cudaDeviceGetAttribute(&nsm, cudaDevAttrMultiProcessorCount, 0);

    const int numTiles = (NFINE + BLOCK_M - 1) / BLOCK_M;
    finefy_tf32_kernel<<<nsm, THREADS, SMEM_BYTES>>>(coarse, nbr, weight, out, numTiles);
}